// round 1
// baseline (speedup 1.0000x reference)
#include <cuda_runtime.h>

// ---------------------------------------------------------------------------
// TNModel: binary tree tensor network, B=65536 samples.
//   x: [B,256,2] f32
//   w7:[128,2,2,4] w6:[64,4,4,8] w5:[32,8,8,8] w4:[16,8,8,8]
//   w3:[8,8,8,8]   w2:[4,8,8,8]  w1:[2,8,8,8]  w0:[8,8,2]
//   out: [B,2] f32
//
// Strategy: one thread = one sample, depth-first streaming over the 64
// level-6 nodes with a register-resident merge stack (5 levels x 8 floats).
// All weights staged in shared memory (164.5 KB), read as warp-uniform
// LDS.128. Arithmetic packed over the k (output) dimension with
// fma.rn.f32x2 (weights pair naturally along k — no repacking).
// ---------------------------------------------------------------------------

#define NB       65536
#define THREADS  512
#define NBLOCKS  (NB / THREADS)   // 128

// shared-memory float offsets
#define O7 0
#define O6 (O7 + 128*2*2*4)        //  2048
#define O5 (O6 + 64*4*4*8)         // 10240
#define O4 (O5 + 32*8*8*8)         // 26624
#define O3 (O4 + 16*8*8*8)         // 34816
#define O2 (O3 + 8*8*8*8)          // 38912
#define O1 (O2 + 4*8*8*8)          // 40960
#define O0 (O1 + 2*8*8*8)          // 41984
#define SMEM_FLOATS (O0 + 8*8*2)   // 42112 floats = 168448 bytes

typedef unsigned long long ull;

__device__ __forceinline__ ull ffma2(ull a, ull b, ull c) {
    ull d;
    asm("fma.rn.f32x2 %0, %1, %2, %3;" : "=l"(d) : "l"(a), "l"(b), "l"(c));
    return d;
}

__device__ __forceinline__ ull bcast2(float x) {
    ull r;
    asm("mov.b64 %0, {%1, %1};" : "=l"(r) : "f"(x));
    return r;
}

__device__ __forceinline__ void unpack2(ull v, float& lo, float& hi) {
    asm("mov.b64 {%0, %1}, %2;" : "=f"(lo), "=f"(hi) : "l"(v));
}

__device__ __forceinline__ void cp8(float* d, const float* s) {
#pragma unroll
    for (int k = 0; k < 8; ++k) d[k] = s[k];
}

// leaf: h[k<4] = sum_{i,j<2} e_i * o_j * w[i*8 + j*4 + k]   (w = 16 floats)
__device__ __forceinline__ void leaf_node(float e0, float e1, float o0, float o1,
                                          const float* __restrict__ w, float* h) {
    ull c0 = 0ull, c1 = 0ull;
    float ev[2] = {e0, e1};
    float ov[2] = {o0, o1};
#pragma unroll
    for (int i = 0; i < 2; ++i) {
#pragma unroll
        for (int j = 0; j < 2; ++j) {
            float p = ev[i] * ov[j];
            ull pp = bcast2(p);
            const ulonglong2 W = *reinterpret_cast<const ulonglong2*>(w + (i * 2 + j) * 4);
            c0 = ffma2(pp, W.x, c0);
            c1 = ffma2(pp, W.y, c1);
        }
    }
    unpack2(c0, h[0], h[1]);
    unpack2(c1, h[2], h[3]);
}

// level-6: out[k<8] = sum_{i,j<4} a_i b_j w[(i*4+j)*8 + k]   (w = 128 floats)
__device__ __forceinline__ void contract448(const float* a, const float* b,
                                            const float* __restrict__ w, float* out) {
    ull c0 = 0ull, c1 = 0ull, c2 = 0ull, c3 = 0ull;
#pragma unroll
    for (int i = 0; i < 4; ++i) {
#pragma unroll
        for (int j = 0; j < 4; ++j) {
            float p = a[i] * b[j];
            ull pp = bcast2(p);
            const ulonglong2* wp = reinterpret_cast<const ulonglong2*>(w + (i * 4 + j) * 8);
            ulonglong2 w01 = wp[0];
            ulonglong2 w23 = wp[1];
            c0 = ffma2(pp, w01.x, c0);
            c1 = ffma2(pp, w01.y, c1);
            c2 = ffma2(pp, w23.x, c2);
            c3 = ffma2(pp, w23.y, c3);
        }
    }
    unpack2(c0, out[0], out[1]);
    unpack2(c1, out[2], out[3]);
    unpack2(c2, out[4], out[5]);
    unpack2(c3, out[6], out[7]);
}

// 8x8 -> 8: out[k<8] = sum_{i,j<8} a_i b_j w[(i*8+j)*8 + k]  (w = 512 floats)
// out may alias b: all reads of b complete before out is written.
__device__ __forceinline__ void contract888(const float* a, const float* b,
                                            const float* __restrict__ w, float* out) {
    ull c0 = 0ull, c1 = 0ull, c2 = 0ull, c3 = 0ull;
#pragma unroll
    for (int i = 0; i < 8; ++i) {
#pragma unroll
        for (int j = 0; j < 8; ++j) {
            float p = a[i] * b[j];
            ull pp = bcast2(p);
            const ulonglong2* wp = reinterpret_cast<const ulonglong2*>(w + (i * 8 + j) * 8);
            ulonglong2 w01 = wp[0];
            ulonglong2 w23 = wp[1];
            c0 = ffma2(pp, w01.x, c0);
            c1 = ffma2(pp, w01.y, c1);
            c2 = ffma2(pp, w23.x, c2);
            c3 = ffma2(pp, w23.y, c3);
        }
    }
    unpack2(c0, out[0], out[1]);
    unpack2(c1, out[2], out[3]);
    unpack2(c2, out[4], out[5]);
    unpack2(c3, out[6], out[7]);
}

__device__ __forceinline__ void scopy4(float* dst, const float* __restrict__ src, int n4) {
    const float4* s = reinterpret_cast<const float4*>(src);
    float4* d = reinterpret_cast<float4*>(dst);
    for (int i = threadIdx.x; i < n4; i += THREADS) d[i] = s[i];
}

__global__ void __launch_bounds__(THREADS, 1)
tn_tree_kernel(const float* __restrict__ x,
               const float* __restrict__ w7, const float* __restrict__ w6,
               const float* __restrict__ w5, const float* __restrict__ w4,
               const float* __restrict__ w3, const float* __restrict__ w2,
               const float* __restrict__ w1, const float* __restrict__ w0,
               float* __restrict__ out) {
    extern __shared__ float sw[];

    // stage all weights into shared memory (warp-uniform broadcast reads later)
    scopy4(sw + O7, w7, (128 * 16) / 4);
    scopy4(sw + O6, w6, (64 * 128) / 4);
    scopy4(sw + O5, w5, (32 * 512) / 4);
    scopy4(sw + O4, w4, (16 * 512) / 4);
    scopy4(sw + O3, w3, (8 * 512) / 4);
    scopy4(sw + O2, w2, (4 * 512) / 4);
    scopy4(sw + O1, w1, (2 * 512) / 4);
    scopy4(sw + O0, w0, (8 * 8 * 2) / 4);
    __syncthreads();

    const int b = blockIdx.x * THREADS + threadIdx.x;
    const float4* xb = reinterpret_cast<const float4*>(x) + (size_t)b * 128;

    float stk0[8], stk1[8], stk2[8], stk3[8], stk4[8];
    float hA[8], hB[8];

#pragma unroll 1
    for (int m = 0; m < 64; ++m) {
        // ---- leaf pair -> level-6 node m ----
        float4 q0 = __ldg(xb + 2 * m);
        float4 q1 = __ldg(xb + 2 * m + 1);
        float ha[4], hb[4];
        leaf_node(q0.x, q0.y, q0.z, q0.w, sw + O7 + (2 * m) * 16, ha);
        leaf_node(q1.x, q1.y, q1.z, q1.w, sw + O7 + (2 * m + 1) * 16, hb);
        float cur[8];
        contract448(ha, hb, sw + O6 + m * 128, cur);

        // ---- merge up the tree (statically unrolled; stack stays in regs) ----
        if (!(m & 1)) {
            cp8(stk0, cur);
        } else {
            contract888(stk0, cur, sw + O5 + (m >> 1) * 512, cur);
            if (!((m >> 1) & 1)) {
                cp8(stk1, cur);
            } else {
                contract888(stk1, cur, sw + O4 + (m >> 2) * 512, cur);
                if (!((m >> 2) & 1)) {
                    cp8(stk2, cur);
                } else {
                    contract888(stk2, cur, sw + O3 + (m >> 3) * 512, cur);
                    if (!((m >> 3) & 1)) {
                        cp8(stk3, cur);
                    } else {
                        contract888(stk3, cur, sw + O2 + (m >> 4) * 512, cur);
                        if (!((m >> 4) & 1)) {
                            cp8(stk4, cur);
                        } else {
                            contract888(stk4, cur, sw + O1 + (m >> 5) * 512, cur);
                            // fully merged half-tree: m == 31 -> node 0, m == 63 -> node 1
                            if (m == 31) cp8(hA, cur);
                            else         cp8(hB, cur);
                        }
                    }
                }
            }
        }
    }

    // ---- root: out[l<2] = sum_{i,j<8} hA_i hB_j w0[(i*8+j)*2 + l] ----
    ull acc = 0ull;
#pragma unroll
    for (int i = 0; i < 8; ++i) {
#pragma unroll
        for (int j = 0; j < 8; ++j) {
            float p = hA[i] * hB[j];
            ull pp = bcast2(p);
            ull W = *reinterpret_cast<const ull*>(sw + O0 + (i * 8 + j) * 2);
            acc = ffma2(pp, W, acc);
        }
    }
    float r0, r1;
    unpack2(acc, r0, r1);
    reinterpret_cast<float2*>(out)[b] = make_float2(r0, r1);
}

extern "C" void kernel_launch(void* const* d_in, const int* in_sizes, int n_in,
                              void* d_out, int out_size) {
    const float* x  = (const float*)d_in[0];
    const float* w7 = (const float*)d_in[1];
    const float* w6 = (const float*)d_in[2];
    const float* w5 = (const float*)d_in[3];
    const float* w4 = (const float*)d_in[4];
    const float* w3 = (const float*)d_in[5];
    const float* w2 = (const float*)d_in[6];
    const float* w1 = (const float*)d_in[7];
    const float* w0 = (const float*)d_in[8];
    float* out = (float*)d_out;

    const size_t smem = SMEM_FLOATS * sizeof(float);
    cudaFuncSetAttribute(tn_tree_kernel, cudaFuncAttributeMaxDynamicSharedMemorySize, (int)smem);
    tn_tree_kernel<<<NBLOCKS, THREADS, smem>>>(x, w7, w6, w5, w4, w3, w2, w1, w0, out);
}

// round 2
// speedup vs baseline: 1.1913x; 1.1913x over previous
#include <cuda_runtime.h>

// ---------------------------------------------------------------------------
// TNModel binary-tree tensor network, B=65536.
// Round 2: 2 samples per thread (halves warp-uniform LDS weight traffic),
// factorized 8x8x8 contraction (t_ik = sum_j b_j W_ijk; out_k += a_i t_ik),
// fma.rn.f32x2 packed over the output dimension k.
// ---------------------------------------------------------------------------

#define NB       65536
#define THREADS  256
#define SPT      2                      // samples per thread
#define NBLOCKS  (NB / (THREADS * SPT)) // 128
#define HALF     (NB / 2)               // 32768

// shared-memory float offsets
#define O7 0
#define O6 (O7 + 128*2*2*4)        //  2048
#define O5 (O6 + 64*4*4*8)         // 10240
#define O4 (O5 + 32*8*8*8)         // 26624
#define O3 (O4 + 16*8*8*8)         // 34816
#define O2 (O3 + 8*8*8*8)          // 38912
#define O1 (O2 + 4*8*8*8)          // 40960
#define O0 (O1 + 2*8*8*8)          // 41984
#define SMEM_FLOATS (O0 + 8*8*2)   // 42112 floats = 168448 bytes

typedef unsigned long long ull;

__device__ __forceinline__ ull ffma2(ull a, ull b, ull c) {
    ull d;
    asm("fma.rn.f32x2 %0, %1, %2, %3;" : "=l"(d) : "l"(a), "l"(b), "l"(c));
    return d;
}

__device__ __forceinline__ ull bcast2(float x) {
    ull r;
    asm("mov.b64 %0, {%1, %1};" : "=l"(r) : "f"(x));
    return r;
}

__device__ __forceinline__ void unpack2(ull v, float& lo, float& hi) {
    asm("mov.b64 {%0, %1}, %2;" : "=f"(lo), "=f"(hi) : "l"(v));
}

__device__ __forceinline__ void cp8(float* d, const float* s) {
#pragma unroll
    for (int k = 0; k < 8; ++k) d[k] = s[k];
}

// --- leaf: two samples share W (16 floats). h[k<4] = sum_{i,j<2} e_i o_j w[ijk]
__device__ __forceinline__ void leaf2(float4 qa, float4 qb,
                                      const float* __restrict__ w,
                                      float* hA, float* hB) {
    ull cA0 = 0, cA1 = 0, cB0 = 0, cB1 = 0;
    float eA[2] = {qa.x, qa.y}, oA[2] = {qa.z, qa.w};
    float eB[2] = {qb.x, qb.y}, oB[2] = {qb.z, qb.w};
#pragma unroll
    for (int i = 0; i < 2; ++i) {
#pragma unroll
        for (int j = 0; j < 2; ++j) {
            const ulonglong2 W = *reinterpret_cast<const ulonglong2*>(w + (i * 2 + j) * 4);
            ull pA = bcast2(eA[i] * oA[j]);
            ull pB = bcast2(eB[i] * oB[j]);
            cA0 = ffma2(pA, W.x, cA0);  cA1 = ffma2(pA, W.y, cA1);
            cB0 = ffma2(pB, W.x, cB0);  cB1 = ffma2(pB, W.y, cB1);
        }
    }
    unpack2(cA0, hA[0], hA[1]);  unpack2(cA1, hA[2], hA[3]);
    unpack2(cB0, hB[0], hB[1]);  unpack2(cB1, hB[2], hB[3]);
}

// --- level-6 (4x4->8), two samples share W (128 floats)
__device__ __forceinline__ void contract448_2(const float* aA, const float* bA,
                                              const float* aB, const float* bB,
                                              const float* __restrict__ w,
                                              float* outA, float* outB) {
    ull cA[4] = {0, 0, 0, 0}, cB[4] = {0, 0, 0, 0};
    ull bbA[4], bbB[4];
#pragma unroll
    for (int j = 0; j < 4; ++j) { bbA[j] = bcast2(bA[j]); bbB[j] = bcast2(bB[j]); }
#pragma unroll
    for (int i = 0; i < 4; ++i) {
        ull tA[4] = {0, 0, 0, 0}, tB[4] = {0, 0, 0, 0};
#pragma unroll
        for (int j = 0; j < 4; ++j) {
            const ulonglong2* wp = reinterpret_cast<const ulonglong2*>(w + (i * 4 + j) * 8);
            ulonglong2 W01 = wp[0];
            ulonglong2 W23 = wp[1];
            tA[0] = ffma2(bbA[j], W01.x, tA[0]);  tA[1] = ffma2(bbA[j], W01.y, tA[1]);
            tA[2] = ffma2(bbA[j], W23.x, tA[2]);  tA[3] = ffma2(bbA[j], W23.y, tA[3]);
            tB[0] = ffma2(bbB[j], W01.x, tB[0]);  tB[1] = ffma2(bbB[j], W01.y, tB[1]);
            tB[2] = ffma2(bbB[j], W23.x, tB[2]);  tB[3] = ffma2(bbB[j], W23.y, tB[3]);
        }
        ull aiA = bcast2(aA[i]), aiB = bcast2(aB[i]);
#pragma unroll
        for (int k = 0; k < 4; ++k) {
            cA[k] = ffma2(aiA, tA[k], cA[k]);
            cB[k] = ffma2(aiB, tB[k], cB[k]);
        }
    }
    unpack2(cA[0], outA[0], outA[1]);  unpack2(cA[1], outA[2], outA[3]);
    unpack2(cA[2], outA[4], outA[5]);  unpack2(cA[3], outA[6], outA[7]);
    unpack2(cB[0], outB[0], outB[1]);  unpack2(cB[1], outB[2], outB[3]);
    unpack2(cB[2], outB[4], outB[5]);  unpack2(cB[3], outB[6], outB[7]);
}

// --- 8x8->8, two samples share W (512 floats). out may alias b.
__device__ __forceinline__ void contract888_2(const float* aA, const float* bA,
                                              const float* aB, const float* bB,
                                              const float* __restrict__ w,
                                              float* outA, float* outB) {
    ull cA[4] = {0, 0, 0, 0}, cB[4] = {0, 0, 0, 0};
    ull bbA[8], bbB[8];
#pragma unroll
    for (int j = 0; j < 8; ++j) { bbA[j] = bcast2(bA[j]); bbB[j] = bcast2(bB[j]); }
#pragma unroll
    for (int i = 0; i < 8; ++i) {
        ull tA[4] = {0, 0, 0, 0}, tB[4] = {0, 0, 0, 0};
        const float* base = w + i * 64;
#pragma unroll
        for (int j = 0; j < 8; ++j) {
            const ulonglong2* wp = reinterpret_cast<const ulonglong2*>(base + j * 8);
            ulonglong2 W01 = wp[0];
            ulonglong2 W23 = wp[1];
            tA[0] = ffma2(bbA[j], W01.x, tA[0]);  tA[1] = ffma2(bbA[j], W01.y, tA[1]);
            tA[2] = ffma2(bbA[j], W23.x, tA[2]);  tA[3] = ffma2(bbA[j], W23.y, tA[3]);
            tB[0] = ffma2(bbB[j], W01.x, tB[0]);  tB[1] = ffma2(bbB[j], W01.y, tB[1]);
            tB[2] = ffma2(bbB[j], W23.x, tB[2]);  tB[3] = ffma2(bbB[j], W23.y, tB[3]);
        }
        ull aiA = bcast2(aA[i]), aiB = bcast2(aB[i]);
#pragma unroll
        for (int k = 0; k < 4; ++k) {
            cA[k] = ffma2(aiA, tA[k], cA[k]);
            cB[k] = ffma2(aiB, tB[k], cB[k]);
        }
    }
    unpack2(cA[0], outA[0], outA[1]);  unpack2(cA[1], outA[2], outA[3]);
    unpack2(cA[2], outA[4], outA[5]);  unpack2(cA[3], outA[6], outA[7]);
    unpack2(cB[0], outB[0], outB[1]);  unpack2(cB[1], outB[2], outB[3]);
    unpack2(cB[2], outB[4], outB[5]);  unpack2(cB[3], outB[6], outB[7]);
}

__device__ __forceinline__ void scopy4(float* dst, const float* __restrict__ src, int n4) {
    const float4* s = reinterpret_cast<const float4*>(src);
    float4* d = reinterpret_cast<float4*>(dst);
    for (int i = threadIdx.x; i < n4; i += THREADS) d[i] = s[i];
}

__global__ void __launch_bounds__(THREADS, 1)
tn_tree_kernel(const float* __restrict__ x,
               const float* __restrict__ w7, const float* __restrict__ w6,
               const float* __restrict__ w5, const float* __restrict__ w4,
               const float* __restrict__ w3, const float* __restrict__ w2,
               const float* __restrict__ w1, const float* __restrict__ w0,
               float* __restrict__ out) {
    extern __shared__ float sw[];

    scopy4(sw + O7, w7, (128 * 16) / 4);
    scopy4(sw + O6, w6, (64 * 128) / 4);
    scopy4(sw + O5, w5, (32 * 512) / 4);
    scopy4(sw + O4, w4, (16 * 512) / 4);
    scopy4(sw + O3, w3, (8 * 512) / 4);
    scopy4(sw + O2, w2, (4 * 512) / 4);
    scopy4(sw + O1, w1, (2 * 512) / 4);
    scopy4(sw + O0, w0, (8 * 8 * 2) / 4);
    __syncthreads();

    const int bA = blockIdx.x * THREADS + threadIdx.x;   // sample A
    const int bB = bA + HALF;                            // sample B
    const float4* xA = reinterpret_cast<const float4*>(x) + (size_t)bA * 128;
    const float4* xB = reinterpret_cast<const float4*>(x) + (size_t)bB * 128;

    float stkA0[8], stkA1[8], stkA2[8], stkA3[8], stkA4[8];
    float stkB0[8], stkB1[8], stkB2[8], stkB3[8], stkB4[8];
    float hAA[8], hAB[8];   // sample A: left/right half-tree results
    float hBA[8], hBB[8];   // sample B

#pragma unroll 1
    for (int m = 0; m < 64; ++m) {
        // ---- two leaves -> one level-6 node, both samples ----
        float4 qA0 = __ldg(xA + 2 * m);
        float4 qA1 = __ldg(xA + 2 * m + 1);
        float4 qB0 = __ldg(xB + 2 * m);
        float4 qB1 = __ldg(xB + 2 * m + 1);

        float laA[4], lbA[4], laB[4], lbB[4];
        leaf2(qA0, qB0, sw + O7 + (2 * m) * 16, laA, laB);
        leaf2(qA1, qB1, sw + O7 + (2 * m + 1) * 16, lbA, lbB);

        float curA[8], curB[8];
        contract448_2(laA, lbA, laB, lbB, sw + O6 + m * 128, curA, curB);

        // ---- merge up the tree ----
        if (!(m & 1)) {
            cp8(stkA0, curA);  cp8(stkB0, curB);
        } else {
            contract888_2(stkA0, curA, stkB0, curB, sw + O5 + (m >> 1) * 512, curA, curB);
            if (!((m >> 1) & 1)) {
                cp8(stkA1, curA);  cp8(stkB1, curB);
            } else {
                contract888_2(stkA1, curA, stkB1, curB, sw + O4 + (m >> 2) * 512, curA, curB);
                if (!((m >> 2) & 1)) {
                    cp8(stkA2, curA);  cp8(stkB2, curB);
                } else {
                    contract888_2(stkA2, curA, stkB2, curB, sw + O3 + (m >> 3) * 512, curA, curB);
                    if (!((m >> 3) & 1)) {
                        cp8(stkA3, curA);  cp8(stkB3, curB);
                    } else {
                        contract888_2(stkA3, curA, stkB3, curB, sw + O2 + (m >> 4) * 512, curA, curB);
                        if (!((m >> 4) & 1)) {
                            cp8(stkA4, curA);  cp8(stkB4, curB);
                        } else {
                            contract888_2(stkA4, curA, stkB4, curB, sw + O1 + (m >> 5) * 512, curA, curB);
                            if (m == 31) { cp8(hAA, curA); cp8(hBA, curB); }
                            else         { cp8(hAB, curA); cp8(hBB, curB); }
                        }
                    }
                }
            }
        }
    }

    // ---- root: out[l<2] = sum_{i,j<8} hL_i hR_j w0[(i*8+j)*2 + l], both samples ----
    ull accA = 0, accB = 0;
#pragma unroll
    for (int i = 0; i < 8; ++i) {
        ull aiA = bcast2(hAA[i]);
        ull aiB = bcast2(hBA[i]);
#pragma unroll
        for (int j = 0; j < 8; ++j) {
            ull W = *reinterpret_cast<const ull*>(sw + O0 + (i * 8 + j) * 2);
            accA = ffma2(ffma2(aiA, bcast2(hAB[j]), 0ull) , W, accA);
            accB = ffma2(ffma2(aiB, bcast2(hBB[j]), 0ull) , W, accB);
        }
    }
    float rA0, rA1, rB0, rB1;
    unpack2(accA, rA0, rA1);
    unpack2(accB, rB0, rB1);
    reinterpret_cast<float2*>(out)[bA] = make_float2(rA0, rA1);
    reinterpret_cast<float2*>(out)[bB] = make_float2(rB0, rB1);
}

extern "C" void kernel_launch(void* const* d_in, const int* in_sizes, int n_in,
                              void* d_out, int out_size) {
    const float* x  = (const float*)d_in[0];
    const float* w7 = (const float*)d_in[1];
    const float* w6 = (const float*)d_in[2];
    const float* w5 = (const float*)d_in[3];
    const float* w4 = (const float*)d_in[4];
    const float* w3 = (const float*)d_in[5];
    const float* w2 = (const float*)d_in[6];
    const float* w1 = (const float*)d_in[7];
    const float* w0 = (const float*)d_in[8];
    float* out = (float*)d_out;

    const size_t smem = SMEM_FLOATS * sizeof(float);
    cudaFuncSetAttribute(tn_tree_kernel, cudaFuncAttributeMaxDynamicSharedMemorySize, (int)smem);
    tn_tree_kernel<<<NBLOCKS, THREADS, smem>>>(x, w7, w6, w5, w4, w3, w2, w1, w0, out);
}